// round 12
// baseline (speedup 1.0000x reference)
#include <cuda_runtime.h>

typedef unsigned long long u64;

#define DD 17
#define HH 8
#define OO 6
#define EE 4

// __constant__: GW1 + GW2 only (2 memcpy nodes)
#define C_GW1 0            // 1088
#define C_GW2 1088         // 2048
__constant__ __align__(16) float cw[3136];

// shared: expert weights (divergent), small gating params, staged x tiles
#define S_EW1 0            // 544
#define S_EB1 544          // 32
#define S_EW2 576          // 256
#define S_EB2 832          // 32
#define S_EW3 864          // 192
#define S_EB3 1056         // 24 -> pad 1088
#define S_GB1 1088         // 64
#define S_GB2 1152         // 32
#define S_GW3 1184         // 128
#define S_GB3 1312         // 4 -> pad 1328
#define S_XA  1328         // 2176
#define S_XB  3504         // 2176
#define S_TOT 5680

__device__ __forceinline__ u64 pk2(float lo, float hi) {
    u64 r; asm("mov.b64 %0, {%1,%2};" : "=l"(r) : "f"(lo), "f"(hi)); return r;
}
__device__ __forceinline__ u64 dup2(float v) { return pk2(v, v); }
__device__ __forceinline__ void upk2(u64 v, float& lo, float& hi) {
    asm("mov.b64 {%0,%1}, %2;" : "=f"(lo), "=f"(hi) : "l"(v));
}
__device__ __forceinline__ u64 ffma2(u64 a, u64 b, u64 c) {
    u64 d; asm("fma.rn.f32x2 %0, %1, %2, %3;" : "=l"(d) : "l"(a), "l"(b), "l"(c)); return d;
}

// selected-expert MLP; weights from smem, x from registers
__device__ __forceinline__ void expert_eval(const float* __restrict__ s,
                                            const float xv[DD], int sel,
                                            u64& o0, u64& o1, u64& o2)
{
    u64 e1p[4];
    {
        const ulonglong2* bp = (const ulonglong2*)&s[S_EB1 + sel * HH];
        ulonglong2 v0 = bp[0], v1 = bp[1];
        e1p[0] = v0.x; e1p[1] = v0.y; e1p[2] = v1.x; e1p[3] = v1.y;
    }
#pragma unroll
    for (int i = 0; i < DD; i++) {
        const u64 xi2 = dup2(xv[i]);
        const ulonglong2* wp = (const ulonglong2*)&s[S_EW1 + (sel * DD + i) * HH];
        ulonglong2 w0 = wp[0], w1 = wp[1];
        // src0 = xi2 for all four -> reuse run of 4
        e1p[0] = ffma2(xi2, w0.x, e1p[0]);
        e1p[1] = ffma2(xi2, w0.y, e1p[1]);
        e1p[2] = ffma2(xi2, w1.x, e1p[2]);
        e1p[3] = ffma2(xi2, w1.y, e1p[3]);
    }
    float e1[HH];
    upk2(e1p[0], e1[0], e1[1]); upk2(e1p[1], e1[2], e1[3]);
    upk2(e1p[2], e1[4], e1[5]); upk2(e1p[3], e1[6], e1[7]);
#pragma unroll
    for (int h = 0; h < HH; h++) e1[h] = fmaxf(e1[h], 0.0f);

    u64 e2p[4];
    {
        const ulonglong2* bp = (const ulonglong2*)&s[S_EB2 + sel * HH];
        ulonglong2 v0 = bp[0], v1 = bp[1];
        e2p[0] = v0.x; e2p[1] = v0.y; e2p[2] = v1.x; e2p[3] = v1.y;
    }
#pragma unroll
    for (int h = 0; h < HH; h++) {
        const u64 hd = dup2(e1[h]);
        const ulonglong2* wp = (const ulonglong2*)&s[S_EW2 + (sel * HH + h) * HH];
        ulonglong2 w0 = wp[0], w1 = wp[1];
        e2p[0] = ffma2(hd, w0.x, e2p[0]);
        e2p[1] = ffma2(hd, w0.y, e2p[1]);
        e2p[2] = ffma2(hd, w1.x, e2p[2]);
        e2p[3] = ffma2(hd, w1.y, e2p[3]);
    }
    float e2[HH];
    upk2(e2p[0], e2[0], e2[1]); upk2(e2p[1], e2[2], e2[3]);
    upk2(e2p[2], e2[4], e2[5]); upk2(e2p[3], e2[6], e2[7]);
#pragma unroll
    for (int k = 0; k < HH; k++) e2[k] = fmaxf(e2[k], 0.0f);

    {
        const u64* bp = (const u64*)&s[S_EB3 + sel * OO];
        o0 = bp[0]; o1 = bp[1]; o2 = bp[2];
    }
#pragma unroll
    for (int k = 0; k < HH; k++) {
        const u64 kd = dup2(e2[k]);
        const u64* wp = (const u64*)&s[S_EW3 + (sel * HH + k) * OO];
        o0 = ffma2(kd, wp[0], o0);
        o1 = ffma2(kd, wp[1], o1);
        o2 = ffma2(kd, wp[2], o2);
    }
}

__global__ __launch_bounds__(128, 4) void moe_kernel(
    const float* __restrict__ x,
    const float* __restrict__ eW1, const float* __restrict__ eb1,
    const float* __restrict__ eW2, const float* __restrict__ eb2,
    const float* __restrict__ eW3, const float* __restrict__ eb3,
    const float* __restrict__ gb1, const float* __restrict__ gb2,
    const float* __restrict__ gW3, const float* __restrict__ gb3,
    float* __restrict__ pred, float* __restrict__ glog, int Bhalf)
{
    __shared__ __align__(16) float s[S_TOT];
    const int t = threadIdx.x;
    for (int i = t; i < 544; i += 128) s[S_EW1 + i] = eW1[i];
    if (t < 32)  s[S_EB1 + t] = eb1[t];
    for (int i = t; i < 256; i += 128) s[S_EW2 + i] = eW2[i];
    if (t >= 32 && t < 64) s[S_EB2 + (t - 32)] = eb2[t - 32];
    for (int i = t; i < 192; i += 128) s[S_EW3 + i] = eW3[i];
    if (t >= 64 && t < 88) s[S_EB3 + (t - 64)] = eb3[t - 64];
    if (t < 64)  s[S_GB1 + t] = gb1[t];
    if (t >= 64 && t < 96) s[S_GB2 + (t - 64)] = gb2[t - 64];
    s[S_GW3 + t] = gW3[t];
    if (t >= 96 && t < 100) s[S_GB3 + (t - 96)] = gb3[t - 96];
    {
        const float4* srcA = (const float4*)(x + (size_t)blockIdx.x * 128 * DD);
        const float4* srcB = (const float4*)(x + ((size_t)blockIdx.x * 128 + (size_t)Bhalf) * DD);
        float4* dA = (float4*)&s[S_XA];
        float4* dB = (float4*)&s[S_XB];
        for (int i = t; i < 544; i += 128) { dA[i] = srcA[i]; dB[i] = srcB[i]; }
    }
    __syncthreads();

    const int ba = blockIdx.x * 128 + t;
    const int bb = ba + Bhalf;

    // x rows: smem -> registers ONCE
    float xa[DD], xb[DD];
#pragma unroll
    for (int i = 0; i < DD; i++) {
        xa[i] = s[S_XA + t * DD + i];
        xb[i] = s[S_XB + t * DD + i];
    }

    u64 A2[16], B2[16];
    {
        const ulonglong2* bp = (const ulonglong2*)&s[S_GB2];
#pragma unroll
        for (int q = 0; q < 8; q++) {
            ulonglong2 v = bp[q];
            A2[2*q]   = v.x; B2[2*q]   = v.x;
            A2[2*q+1] = v.y; B2[2*q+1] = v.y;
        }
    }

    // layer1 (16-neuron chunks, GW1 const) fused into layer2 (GW2 const)
    // ALL inner bodies grouped into same-multiplier runs of 4 for src0 reuse.
#pragma unroll
    for (int c = 0; c < 4; c++) {
        u64 A1[8], B1[8];
        {
            const ulonglong2* bp = (const ulonglong2*)&s[S_GB1 + c * 16];
#pragma unroll
            for (int q = 0; q < 4; q++) {
                ulonglong2 v = bp[q];
                A1[2*q] = v.x; A1[2*q+1] = v.y;
                B1[2*q] = v.x; B1[2*q+1] = v.y;
            }
        }
#pragma unroll
        for (int i = 0; i < DD; i++) {
            const u64 xad = dup2(xa[i]);
            const u64 xbd = dup2(xb[i]);
            const ulonglong2* wp = (const ulonglong2*)&cw[C_GW1 + i * 64 + c * 16];
            ulonglong2 w0 = wp[0], w1 = wp[1];
            // A-run (src0 = xad, 4 in a row)
            A1[0] = ffma2(xad, w0.x, A1[0]);
            A1[1] = ffma2(xad, w0.y, A1[1]);
            A1[2] = ffma2(xad, w1.x, A1[2]);
            A1[3] = ffma2(xad, w1.y, A1[3]);
            // B-run (src0 = xbd)
            B1[0] = ffma2(xbd, w0.x, B1[0]);
            B1[1] = ffma2(xbd, w0.y, B1[1]);
            B1[2] = ffma2(xbd, w1.x, B1[2]);
            B1[3] = ffma2(xbd, w1.y, B1[3]);
            ulonglong2 w2 = wp[2], w3 = wp[3];
            A1[4] = ffma2(xad, w2.x, A1[4]);
            A1[5] = ffma2(xad, w2.y, A1[5]);
            A1[6] = ffma2(xad, w3.x, A1[6]);
            A1[7] = ffma2(xad, w3.y, A1[7]);
            B1[4] = ffma2(xbd, w2.x, B1[4]);
            B1[5] = ffma2(xbd, w2.y, B1[5]);
            B1[6] = ffma2(xbd, w3.x, B1[6]);
            B1[7] = ffma2(xbd, w3.y, B1[7]);
        }
        // relu + feed into layer 2 (GW2 const rows of 32), same-multiplier runs of 4
#pragma unroll
        for (int p = 0; p < 8; p++) {
            float a0, a1, b0, b1;
            upk2(A1[p], a0, a1);
            upk2(B1[p], b0, b1);
#pragma unroll
            for (int half = 0; half < 2; half++) {
                const u64 had = dup2(fmaxf(half ? a1 : a0, 0.0f));
                const u64 hbd = dup2(fmaxf(half ? b1 : b0, 0.0f));
                const int j = c * 16 + 2 * p + half;
                const ulonglong2* wp = (const ulonglong2*)&cw[C_GW2 + j * 32];
#pragma unroll
                for (int q2 = 0; q2 < 2; q2++) {
                    ulonglong2 w0 = wp[4*q2+0], w1 = wp[4*q2+1];
                    A2[8*q2+0] = ffma2(had, w0.x, A2[8*q2+0]);
                    A2[8*q2+1] = ffma2(had, w0.y, A2[8*q2+1]);
                    A2[8*q2+2] = ffma2(had, w1.x, A2[8*q2+2]);
                    A2[8*q2+3] = ffma2(had, w1.y, A2[8*q2+3]);
                    B2[8*q2+0] = ffma2(hbd, w0.x, B2[8*q2+0]);
                    B2[8*q2+1] = ffma2(hbd, w0.y, B2[8*q2+1]);
                    B2[8*q2+2] = ffma2(hbd, w1.x, B2[8*q2+2]);
                    B2[8*q2+3] = ffma2(hbd, w1.y, B2[8*q2+3]);
                    ulonglong2 w2 = wp[4*q2+2], w3 = wp[4*q2+3];
                    A2[8*q2+4] = ffma2(had, w2.x, A2[8*q2+4]);
                    A2[8*q2+5] = ffma2(had, w2.y, A2[8*q2+5]);
                    A2[8*q2+6] = ffma2(had, w3.x, A2[8*q2+6]);
                    A2[8*q2+7] = ffma2(had, w3.y, A2[8*q2+7]);
                    B2[8*q2+4] = ffma2(hbd, w2.x, B2[8*q2+4]);
                    B2[8*q2+5] = ffma2(hbd, w2.y, B2[8*q2+5]);
                    B2[8*q2+6] = ffma2(hbd, w3.x, B2[8*q2+6]);
                    B2[8*q2+7] = ffma2(hbd, w3.y, B2[8*q2+7]);
                }
            }
        }
    }

    // layer 3: relu(h2) -> 4 logits (GW3/gb3 from smem), runs of 2 per multiplier
    u64 lgA0, lgA1, lgB0, lgB1;
    {
        ulonglong2 bv = *(const ulonglong2*)&s[S_GB3];
        lgA0 = bv.x; lgA1 = bv.y;
        lgB0 = bv.x; lgB1 = bv.y;
    }
#pragma unroll
    for (int p = 0; p < 16; p++) {
        float a0, a1, b0, b1;
        upk2(A2[p], a0, a1);
        upk2(B2[p], b0, b1);
#pragma unroll
        for (int half = 0; half < 2; half++) {
            const u64 had = dup2(fmaxf(half ? a1 : a0, 0.0f));
            const u64 hbd = dup2(fmaxf(half ? b1 : b0, 0.0f));
            const int k = 2 * p + half;
            ulonglong2 w = *(const ulonglong2*)&s[S_GW3 + k * 4];
            lgA0 = ffma2(had, w.x, lgA0);
            lgA1 = ffma2(had, w.y, lgA1);
            lgB0 = ffma2(hbd, w.x, lgB0);
            lgB1 = ffma2(hbd, w.y, lgB1);
        }
    }

    // argmax (first-max-wins, matches jnp.argmax)
    float la0, la1, la2, la3, lb0, lb1, lb2, lb3;
    upk2(lgA0, la0, la1); upk2(lgA1, la2, la3);
    upk2(lgB0, lb0, lb1); upk2(lgB1, lb2, lb3);
    int selA = 0; float mA = la0;
    if (la1 > mA) { mA = la1; selA = 1; }
    if (la2 > mA) { mA = la2; selA = 2; }
    if (la3 > mA) { mA = la3; selA = 3; }
    int selB = 0; float mB = lb0;
    if (lb1 > mB) { mB = lb1; selB = 1; }
    if (lb2 > mB) { mB = lb2; selB = 2; }
    if (lb3 > mB) { mB = lb3; selB = 3; }

    u64 oA0, oA1, oA2, oB0, oB1, oB2;
    expert_eval(s, xa, selA, oA0, oA1, oA2);
    expert_eval(s, xb, selB, oB0, oB1, oB2);

    {
        u64* p0 = (u64*)(pred + (size_t)ba * OO);
        p0[0] = oA0; p0[1] = oA1; p0[2] = oA2;
        u64* p1 = (u64*)(pred + (size_t)bb * OO);
        p1[0] = oB0; p1[1] = oB1; p1[2] = oB2;
        ulonglong2* l0 = (ulonglong2*)(glog + (size_t)ba * EE);
        l0[0] = make_ulonglong2(lgA0, lgA1);
        ulonglong2* l1 = (ulonglong2*)(glog + (size_t)bb * EE);
        l1[0] = make_ulonglong2(lgB0, lgB1);
    }
}

extern "C" void kernel_launch(void* const* d_in, const int* in_sizes, int n_in,
                              void* d_out, int out_size) {
    const float* x   = (const float*)d_in[0];
    const float* eW1 = (const float*)d_in[1];
    const float* eb1 = (const float*)d_in[2];
    const float* eW2 = (const float*)d_in[3];
    const float* eb2 = (const float*)d_in[4];
    const float* eW3 = (const float*)d_in[5];
    const float* eb3 = (const float*)d_in[6];
    const float* gW1 = (const float*)d_in[7];
    const float* gb1 = (const float*)d_in[8];
    const float* gW2 = (const float*)d_in[9];
    const float* gb2 = (const float*)d_in[10];
    const float* gW3 = (const float*)d_in[11];
    const float* gb3 = (const float*)d_in[12];

    cudaMemcpyToSymbolAsync(cw, gW1, 1088 * 4, C_GW1 * 4, cudaMemcpyDeviceToDevice);
    cudaMemcpyToSymbolAsync(cw, gW2, 2048 * 4, C_GW2 * 4, cudaMemcpyDeviceToDevice);

    const int B = in_sizes[0] / DD;
    float* out  = (float*)d_out;
    float* pred = out;                   // [B, 6]
    float* glog = out + (size_t)B * OO;  // [B, 4]

    const int grid = B / 256;            // 128 threads/block, 2 samples/thread
    moe_kernel<<<grid, 128>>>(x, eW1, eb1, eW2, eb2, eW3, eb3,
                              gb1, gb2, gW3, gb3, pred, glog, B / 2);
}

// round 13
// speedup vs baseline: 1.0144x; 1.0144x over previous
#include <cuda_runtime.h>

typedef unsigned long long u64;

#define DD 17
#define HH 8
#define OO 6
#define EE 4

// __constant__: GW1 + GW2 only (2 memcpy graph nodes)
#define C_GW1 0            // 1088
#define C_GW2 1088         // 2048
__constant__ __align__(16) float cw[3136];

// shared: expert weights (divergent) + small gating params
#define S_EW1 0            // 544
#define S_EB1 544          // 32
#define S_EW2 576          // 256
#define S_EB2 832          // 32
#define S_EW3 864          // 192
#define S_EB3 1056         // 24 -> pad 1088
#define S_GB1 1088         // 64
#define S_GB2 1152         // 32
#define S_GW3 1184         // 128
#define S_GB3 1312         // 4 -> pad 1328
#define S_TOT 1328

__device__ __forceinline__ u64 pk2(float lo, float hi) {
    u64 r; asm("mov.b64 %0, {%1,%2};" : "=l"(r) : "f"(lo), "f"(hi)); return r;
}
__device__ __forceinline__ u64 dup2(float v) { return pk2(v, v); }
__device__ __forceinline__ void upk2(u64 v, float& lo, float& hi) {
    asm("mov.b64 {%0,%1}, %2;" : "=f"(lo), "=f"(hi) : "l"(v));
}
__device__ __forceinline__ u64 ffma2(u64 a, u64 b, u64 c) {
    u64 d; asm("fma.rn.f32x2 %0, %1, %2, %3;" : "=l"(d) : "l"(a), "l"(b), "l"(c)); return d;
}

// selected-expert MLP (smem weights, divergent by sel; x from registers)
__device__ __forceinline__ void expert_eval(const float* __restrict__ s,
                                            const float xv[DD], int sel,
                                            u64& o0, u64& o1, u64& o2)
{
    u64 e1p[4];
    {
        const ulonglong2* bp = (const ulonglong2*)&s[S_EB1 + sel * HH];
        ulonglong2 v0 = bp[0], v1 = bp[1];
        e1p[0] = v0.x; e1p[1] = v0.y; e1p[2] = v1.x; e1p[3] = v1.y;
    }
#pragma unroll
    for (int i = 0; i < DD; i++) {
        const u64 xi2 = dup2(xv[i]);
        const ulonglong2* wp = (const ulonglong2*)&s[S_EW1 + (sel * DD + i) * HH];
        ulonglong2 w0 = wp[0], w1 = wp[1];
        e1p[0] = ffma2(xi2, w0.x, e1p[0]);
        e1p[1] = ffma2(xi2, w0.y, e1p[1]);
        e1p[2] = ffma2(xi2, w1.x, e1p[2]);
        e1p[3] = ffma2(xi2, w1.y, e1p[3]);
    }
    float e1[HH];
    upk2(e1p[0], e1[0], e1[1]); upk2(e1p[1], e1[2], e1[3]);
    upk2(e1p[2], e1[4], e1[5]); upk2(e1p[3], e1[6], e1[7]);
#pragma unroll
    for (int h = 0; h < HH; h++) e1[h] = fmaxf(e1[h], 0.0f);

    u64 e2p[4];
    {
        const ulonglong2* bp = (const ulonglong2*)&s[S_EB2 + sel * HH];
        ulonglong2 v0 = bp[0], v1 = bp[1];
        e2p[0] = v0.x; e2p[1] = v0.y; e2p[2] = v1.x; e2p[3] = v1.y;
    }
#pragma unroll
    for (int h = 0; h < HH; h++) {
        const u64 hd = dup2(e1[h]);
        const ulonglong2* wp = (const ulonglong2*)&s[S_EW2 + (sel * HH + h) * HH];
        ulonglong2 w0 = wp[0], w1 = wp[1];
        e2p[0] = ffma2(hd, w0.x, e2p[0]);
        e2p[1] = ffma2(hd, w0.y, e2p[1]);
        e2p[2] = ffma2(hd, w1.x, e2p[2]);
        e2p[3] = ffma2(hd, w1.y, e2p[3]);
    }
    float e2[HH];
    upk2(e2p[0], e2[0], e2[1]); upk2(e2p[1], e2[2], e2[3]);
    upk2(e2p[2], e2[4], e2[5]); upk2(e2p[3], e2[6], e2[7]);
#pragma unroll
    for (int k = 0; k < HH; k++) e2[k] = fmaxf(e2[k], 0.0f);

    {
        const u64* bp = (const u64*)&s[S_EB3 + sel * OO];
        o0 = bp[0]; o1 = bp[1]; o2 = bp[2];
    }
#pragma unroll
    for (int k = 0; k < HH; k++) {
        const u64 kd = dup2(e2[k]);
        const u64* wp = (const u64*)&s[S_EW3 + (sel * HH + k) * OO];
        o0 = ffma2(kd, wp[0], o0);
        o1 = ffma2(kd, wp[1], o1);
        o2 = ffma2(kd, wp[2], o2);
    }
}

__global__ __launch_bounds__(128, 4) void moe_kernel(
    const float* __restrict__ x,
    const float* __restrict__ eW1, const float* __restrict__ eb1,
    const float* __restrict__ eW2, const float* __restrict__ eb2,
    const float* __restrict__ eW3, const float* __restrict__ eb3,
    const float* __restrict__ gb1, const float* __restrict__ gb2,
    const float* __restrict__ gW3, const float* __restrict__ gb3,
    float* __restrict__ pred, float* __restrict__ glog, int Bhalf)
{
    __shared__ __align__(16) float s[S_TOT];
    const int t = threadIdx.x;
    // expert weights -> smem
    for (int i = t; i < 544; i += 128) s[S_EW1 + i] = eW1[i];
    if (t < 32)  s[S_EB1 + t] = eb1[t];
    for (int i = t; i < 256; i += 128) s[S_EW2 + i] = eW2[i];
    if (t >= 32 && t < 64) s[S_EB2 + (t - 32)] = eb2[t - 32];
    for (int i = t; i < 192; i += 128) s[S_EW3 + i] = eW3[i];
    if (t >= 64 && t < 88) s[S_EB3 + (t - 64)] = eb3[t - 64];
    // small gating params -> smem
    if (t < 64)  s[S_GB1 + t] = gb1[t];
    if (t >= 64 && t < 96) s[S_GB2 + (t - 64)] = gb2[t - 64];
    s[S_GW3 + t] = gW3[t];
    if (t >= 96 && t < 100) s[S_GB3 + (t - 96)] = gb3[t - 96];
    __syncthreads();

    const int ba = blockIdx.x * 128 + t;   // first sample
    const int bb = ba + Bhalf;             // second sample (coalesced pairing)

    // x rows: direct per-thread global loads (R4-style; streaming, cache-neutral)
    float xa[DD], xb[DD];
    {
        const float* ra = x + (size_t)ba * DD;
        const float* rb = x + (size_t)bb * DD;
#pragma unroll
        for (int i = 0; i < DD; i++) { xa[i] = ra[i]; xb[i] = rb[i]; }
    }

    // gating layer-2 accumulators (bias from smem broadcast)
    u64 A2[16], B2[16];
    {
        const ulonglong2* bp = (const ulonglong2*)&s[S_GB2];
#pragma unroll
        for (int q = 0; q < 8; q++) {
            ulonglong2 v = bp[q];
            A2[2*q]   = v.x; B2[2*q]   = v.x;
            A2[2*q+1] = v.y; B2[2*q+1] = v.y;
        }
    }

    // layer1 in 16-neuron chunks (GW1 const), fused into layer2 (GW2 const) — R4 structure
#pragma unroll
    for (int c = 0; c < 4; c++) {
        u64 A1[8], B1[8];
        {
            const ulonglong2* bp = (const ulonglong2*)&s[S_GB1 + c * 16];
#pragma unroll
            for (int q = 0; q < 4; q++) {
                ulonglong2 v = bp[q];
                A1[2*q] = v.x; A1[2*q+1] = v.y;
                B1[2*q] = v.x; B1[2*q+1] = v.y;
            }
        }
#pragma unroll
        for (int i = 0; i < DD; i++) {
            const u64 xad = dup2(xa[i]);
            const u64 xbd = dup2(xb[i]);
            const ulonglong2* wp = (const ulonglong2*)&cw[C_GW1 + i * 64 + c * 16];
#pragma unroll
            for (int q = 0; q < 4; q++) {
                ulonglong2 w = wp[q];
                A1[2*q]   = ffma2(xad, w.x, A1[2*q]);
                B1[2*q]   = ffma2(xbd, w.x, B1[2*q]);
                A1[2*q+1] = ffma2(xad, w.y, A1[2*q+1]);
                B1[2*q+1] = ffma2(xbd, w.y, B1[2*q+1]);
            }
        }
        // relu + feed into layer 2 (GW2 const rows of 32)
#pragma unroll
        for (int p = 0; p < 8; p++) {
            float a0, a1, b0, b1;
            upk2(A1[p], a0, a1);
            upk2(B1[p], b0, b1);
#pragma unroll
            for (int half = 0; half < 2; half++) {
                const u64 had = dup2(fmaxf(half ? a1 : a0, 0.0f));
                const u64 hbd = dup2(fmaxf(half ? b1 : b0, 0.0f));
                const int j = c * 16 + 2 * p + half;
                const ulonglong2* wp = (const ulonglong2*)&cw[C_GW2 + j * 32];
#pragma unroll
                for (int q = 0; q < 8; q++) {
                    ulonglong2 w = wp[q];
                    A2[2*q]   = ffma2(had, w.x, A2[2*q]);
                    B2[2*q]   = ffma2(hbd, w.x, B2[2*q]);
                    A2[2*q+1] = ffma2(had, w.y, A2[2*q+1]);
                    B2[2*q+1] = ffma2(hbd, w.y, B2[2*q+1]);
                }
            }
        }
    }

    // layer 3: relu(h2) -> 4 logits (GW3/gb3 from smem)
    u64 lgA0, lgA1, lgB0, lgB1;
    {
        ulonglong2 bv = *(const ulonglong2*)&s[S_GB3];
        lgA0 = bv.x; lgA1 = bv.y;
        lgB0 = bv.x; lgB1 = bv.y;
    }
#pragma unroll
    for (int p = 0; p < 16; p++) {
        float a0, a1, b0, b1;
        upk2(A2[p], a0, a1);
        upk2(B2[p], b0, b1);
#pragma unroll
        for (int half = 0; half < 2; half++) {
            const u64 had = dup2(fmaxf(half ? a1 : a0, 0.0f));
            const u64 hbd = dup2(fmaxf(half ? b1 : b0, 0.0f));
            const int k = 2 * p + half;
            ulonglong2 w = *(const ulonglong2*)&s[S_GW3 + k * 4];
            lgA0 = ffma2(had, w.x, lgA0);
            lgB0 = ffma2(hbd, w.x, lgB0);
            lgA1 = ffma2(had, w.y, lgA1);
            lgB1 = ffma2(hbd, w.y, lgB1);
        }
    }

    // argmax (first-max-wins, matches jnp.argmax)
    float la0, la1, la2, la3, lb0, lb1, lb2, lb3;
    upk2(lgA0, la0, la1); upk2(lgA1, la2, la3);
    upk2(lgB0, lb0, lb1); upk2(lgB1, lb2, lb3);
    int selA = 0; float mA = la0;
    if (la1 > mA) { mA = la1; selA = 1; }
    if (la2 > mA) { mA = la2; selA = 2; }
    if (la3 > mA) { mA = la3; selA = 3; }
    int selB = 0; float mB = lb0;
    if (lb1 > mB) { mB = lb1; selB = 1; }
    if (lb2 > mB) { mB = lb2; selB = 2; }
    if (lb3 > mB) { mB = lb3; selB = 3; }

    u64 oA0, oA1, oA2, oB0, oB1, oB2;
    expert_eval(s, xa, selA, oA0, oA1, oA2);
    expert_eval(s, xb, selB, oB0, oB1, oB2);

    {
        u64* p0 = (u64*)(pred + (size_t)ba * OO);
        p0[0] = oA0; p0[1] = oA1; p0[2] = oA2;
        u64* p1 = (u64*)(pred + (size_t)bb * OO);
        p1[0] = oB0; p1[1] = oB1; p1[2] = oB2;
        ulonglong2* l0 = (ulonglong2*)(glog + (size_t)ba * EE);
        l0[0] = make_ulonglong2(lgA0, lgA1);
        ulonglong2* l1 = (ulonglong2*)(glog + (size_t)bb * EE);
        l1[0] = make_ulonglong2(lgB0, lgB1);
    }
}

extern "C" void kernel_launch(void* const* d_in, const int* in_sizes, int n_in,
                              void* d_out, int out_size) {
    const float* x   = (const float*)d_in[0];
    const float* eW1 = (const float*)d_in[1];
    const float* eb1 = (const float*)d_in[2];
    const float* eW2 = (const float*)d_in[3];
    const float* eb2 = (const float*)d_in[4];
    const float* eW3 = (const float*)d_in[5];
    const float* eb3 = (const float*)d_in[6];
    const float* gW1 = (const float*)d_in[7];
    const float* gb1 = (const float*)d_in[8];
    const float* gW2 = (const float*)d_in[9];
    const float* gb2 = (const float*)d_in[10];
    const float* gW3 = (const float*)d_in[11];
    const float* gb3 = (const float*)d_in[12];

    // two const staging nodes only
    cudaMemcpyToSymbolAsync(cw, gW1, 1088 * 4, C_GW1 * 4, cudaMemcpyDeviceToDevice);
    cudaMemcpyToSymbolAsync(cw, gW2, 2048 * 4, C_GW2 * 4, cudaMemcpyDeviceToDevice);

    const int B = in_sizes[0] / DD;
    float* out  = (float*)d_out;
    float* pred = out;                   // [B, 6]
    float* glog = out + (size_t)B * OO;  // [B, 4]

    const int grid = B / 256;            // 128 threads/block, 2 samples/thread
    moe_kernel<<<grid, 128>>>(x, eW1, eb1, eW2, eb2, eW3, eb3,
                              gb1, gb2, gW3, gb3, pred, glog, B / 2);
}

// round 14
// speedup vs baseline: 1.0765x; 1.0611x over previous
#include <cuda_runtime.h>

typedef unsigned long long u64;

#define DD 17
#define HH 8
#define OO 6
#define EE 4

// __constant__: GW1 + GW2 only (2 memcpy graph nodes)
#define C_GW1 0            // 1088
#define C_GW2 1088         // 2048
__constant__ __align__(16) float cw[3136];

// shared: expert weights (divergent) + small gating params
#define S_EW1 0            // 544
#define S_EB1 544          // 32
#define S_EW2 576          // 256
#define S_EB2 832          // 32
#define S_EW3 864          // 192
#define S_EB3 1056         // 24 -> pad 1088
#define S_GB1 1088         // 64
#define S_GB2 1152         // 32
#define S_GW3 1184         // 128
#define S_GB3 1312         // 4 -> pad 1328
#define S_TOT 1328

__device__ __forceinline__ u64 pk2(float lo, float hi) {
    u64 r; asm("mov.b64 %0, {%1,%2};" : "=l"(r) : "f"(lo), "f"(hi)); return r;
}
__device__ __forceinline__ u64 dup2(float v) { return pk2(v, v); }
__device__ __forceinline__ void upk2(u64 v, float& lo, float& hi) {
    asm("mov.b64 {%0,%1}, %2;" : "=f"(lo), "=f"(hi) : "l"(v));
}
__device__ __forceinline__ u64 ffma2(u64 a, u64 b, u64 c) {
    u64 d; asm("fma.rn.f32x2 %0, %1, %2, %3;" : "=l"(d) : "l"(a), "l"(b), "l"(c)); return d;
}

// selected-expert MLP (smem weights, divergent by sel; x from registers)
__device__ __forceinline__ void expert_eval(const float* __restrict__ s,
                                            const float xv[DD], int sel,
                                            u64& o0, u64& o1, u64& o2)
{
    u64 e1p[4];
    {
        const ulonglong2* bp = (const ulonglong2*)&s[S_EB1 + sel * HH];
        ulonglong2 v0 = bp[0], v1 = bp[1];
        e1p[0] = v0.x; e1p[1] = v0.y; e1p[2] = v1.x; e1p[3] = v1.y;
    }
#pragma unroll
    for (int i = 0; i < DD; i++) {
        const u64 xi2 = dup2(xv[i]);
        const ulonglong2* wp = (const ulonglong2*)&s[S_EW1 + (sel * DD + i) * HH];
        ulonglong2 w0 = wp[0], w1 = wp[1];
        e1p[0] = ffma2(xi2, w0.x, e1p[0]);
        e1p[1] = ffma2(xi2, w0.y, e1p[1]);
        e1p[2] = ffma2(xi2, w1.x, e1p[2]);
        e1p[3] = ffma2(xi2, w1.y, e1p[3]);
    }
    float e1[HH];
    upk2(e1p[0], e1[0], e1[1]); upk2(e1p[1], e1[2], e1[3]);
    upk2(e1p[2], e1[4], e1[5]); upk2(e1p[3], e1[6], e1[7]);
#pragma unroll
    for (int h = 0; h < HH; h++) e1[h] = fmaxf(e1[h], 0.0f);

    u64 e2p[4];
    {
        const ulonglong2* bp = (const ulonglong2*)&s[S_EB2 + sel * HH];
        ulonglong2 v0 = bp[0], v1 = bp[1];
        e2p[0] = v0.x; e2p[1] = v0.y; e2p[2] = v1.x; e2p[3] = v1.y;
    }
#pragma unroll
    for (int h = 0; h < HH; h++) {
        const u64 hd = dup2(e1[h]);
        const ulonglong2* wp = (const ulonglong2*)&s[S_EW2 + (sel * HH + h) * HH];
        ulonglong2 w0 = wp[0], w1 = wp[1];
        e2p[0] = ffma2(hd, w0.x, e2p[0]);
        e2p[1] = ffma2(hd, w0.y, e2p[1]);
        e2p[2] = ffma2(hd, w1.x, e2p[2]);
        e2p[3] = ffma2(hd, w1.y, e2p[3]);
    }
    float e2[HH];
    upk2(e2p[0], e2[0], e2[1]); upk2(e2p[1], e2[2], e2[3]);
    upk2(e2p[2], e2[4], e2[5]); upk2(e2p[3], e2[6], e2[7]);
#pragma unroll
    for (int k = 0; k < HH; k++) e2[k] = fmaxf(e2[k], 0.0f);

    {
        const u64* bp = (const u64*)&s[S_EB3 + sel * OO];
        o0 = bp[0]; o1 = bp[1]; o2 = bp[2];
    }
#pragma unroll
    for (int k = 0; k < HH; k++) {
        const u64 kd = dup2(e2[k]);
        const u64* wp = (const u64*)&s[S_EW3 + (sel * HH + k) * OO];
        o0 = ffma2(kd, wp[0], o0);
        o1 = ffma2(kd, wp[1], o1);
        o2 = ffma2(kd, wp[2], o2);
    }
}

__global__ __launch_bounds__(128, 3) void moe_kernel(
    const float* __restrict__ x,
    const float* __restrict__ eW1, const float* __restrict__ eb1,
    const float* __restrict__ eW2, const float* __restrict__ eb2,
    const float* __restrict__ eW3, const float* __restrict__ eb3,
    const float* __restrict__ gb1, const float* __restrict__ gb2,
    const float* __restrict__ gW3, const float* __restrict__ gb3,
    float* __restrict__ pred, float* __restrict__ glog, int Bhalf)
{
    __shared__ __align__(16) float s[S_TOT];
    const int t = threadIdx.x;
    // expert weights -> smem
    for (int i = t; i < 544; i += 128) s[S_EW1 + i] = eW1[i];
    if (t < 32)  s[S_EB1 + t] = eb1[t];
    for (int i = t; i < 256; i += 128) s[S_EW2 + i] = eW2[i];
    if (t >= 32 && t < 64) s[S_EB2 + (t - 32)] = eb2[t - 32];
    for (int i = t; i < 192; i += 128) s[S_EW3 + i] = eW3[i];
    if (t >= 64 && t < 88) s[S_EB3 + (t - 64)] = eb3[t - 64];
    // small gating params -> smem
    if (t < 64)  s[S_GB1 + t] = gb1[t];
    if (t >= 64 && t < 96) s[S_GB2 + (t - 64)] = gb2[t - 64];
    s[S_GW3 + t] = gW3[t];
    if (t >= 96 && t < 100) s[S_GB3 + (t - 96)] = gb3[t - 96];
    __syncthreads();

    const int ba = blockIdx.x * 128 + t;   // first sample
    const int bb = ba + Bhalf;             // second sample (coalesced pairing)

    // x rows: direct per-thread global loads into registers
    float xa[DD], xb[DD];
    {
        const float* ra = x + (size_t)ba * DD;
        const float* rb = x + (size_t)bb * DD;
#pragma unroll
        for (int i = 0; i < DD; i++) { xa[i] = ra[i]; xb[i] = rb[i]; }
    }

    // gating layer-2 accumulators (bias from smem broadcast)
    u64 A2[16], B2[16];
    {
        const ulonglong2* bp = (const ulonglong2*)&s[S_GB2];
#pragma unroll
        for (int q = 0; q < 8; q++) {
            ulonglong2 v = bp[q];
            A2[2*q]   = v.x; B2[2*q]   = v.x;
            A2[2*q+1] = v.y; B2[2*q+1] = v.y;
        }
    }

    // layer1 in 16-neuron chunks (GW1 const), fused into layer2 (GW2 const)
#pragma unroll
    for (int c = 0; c < 4; c++) {
        u64 A1[8], B1[8];
        {
            const ulonglong2* bp = (const ulonglong2*)&s[S_GB1 + c * 16];
#pragma unroll
            for (int q = 0; q < 4; q++) {
                ulonglong2 v = bp[q];
                A1[2*q] = v.x; A1[2*q+1] = v.y;
                B1[2*q] = v.x; B1[2*q+1] = v.y;
            }
        }
#pragma unroll
        for (int i = 0; i < DD; i++) {
            const u64 xad = dup2(xa[i]);
            const u64 xbd = dup2(xb[i]);
            const ulonglong2* wp = (const ulonglong2*)&cw[C_GW1 + i * 64 + c * 16];
#pragma unroll
            for (int q = 0; q < 4; q++) {
                ulonglong2 w = wp[q];
                A1[2*q]   = ffma2(xad, w.x, A1[2*q]);
                B1[2*q]   = ffma2(xbd, w.x, B1[2*q]);
                A1[2*q+1] = ffma2(xad, w.y, A1[2*q+1]);
                B1[2*q+1] = ffma2(xbd, w.y, B1[2*q+1]);
            }
        }
        // relu + feed into layer 2 (GW2 const rows of 32)
#pragma unroll
        for (int p = 0; p < 8; p++) {
            float a0, a1, b0, b1;
            upk2(A1[p], a0, a1);
            upk2(B1[p], b0, b1);
#pragma unroll
            for (int half = 0; half < 2; half++) {
                const u64 had = dup2(fmaxf(half ? a1 : a0, 0.0f));
                const u64 hbd = dup2(fmaxf(half ? b1 : b0, 0.0f));
                const int j = c * 16 + 2 * p + half;
                const ulonglong2* wp = (const ulonglong2*)&cw[C_GW2 + j * 32];
#pragma unroll
                for (int q = 0; q < 8; q++) {
                    ulonglong2 w = wp[q];
                    A2[2*q]   = ffma2(had, w.x, A2[2*q]);
                    B2[2*q]   = ffma2(hbd, w.x, B2[2*q]);
                    A2[2*q+1] = ffma2(had, w.y, A2[2*q+1]);
                    B2[2*q+1] = ffma2(hbd, w.y, B2[2*q+1]);
                }
            }
        }
    }

    // layer 3: relu(h2) -> 4 logits (GW3/gb3 from smem)
    u64 lgA0, lgA1, lgB0, lgB1;
    {
        ulonglong2 bv = *(const ulonglong2*)&s[S_GB3];
        lgA0 = bv.x; lgA1 = bv.y;
        lgB0 = bv.x; lgB1 = bv.y;
    }
#pragma unroll
    for (int p = 0; p < 16; p++) {
        float a0, a1, b0, b1;
        upk2(A2[p], a0, a1);
        upk2(B2[p], b0, b1);
#pragma unroll
        for (int half = 0; half < 2; half++) {
            const u64 had = dup2(fmaxf(half ? a1 : a0, 0.0f));
            const u64 hbd = dup2(fmaxf(half ? b1 : b0, 0.0f));
            const int k = 2 * p + half;
            ulonglong2 w = *(const ulonglong2*)&s[S_GW3 + k * 4];
            lgA0 = ffma2(had, w.x, lgA0);
            lgB0 = ffma2(hbd, w.x, lgB0);
            lgA1 = ffma2(had, w.y, lgA1);
            lgB1 = ffma2(hbd, w.y, lgB1);
        }
    }

    // argmax (first-max-wins, matches jnp.argmax)
    float la0, la1, la2, la3, lb0, lb1, lb2, lb3;
    upk2(lgA0, la0, la1); upk2(lgA1, la2, la3);
    upk2(lgB0, lb0, lb1); upk2(lgB1, lb2, lb3);
    int selA = 0; float mA = la0;
    if (la1 > mA) { mA = la1; selA = 1; }
    if (la2 > mA) { mA = la2; selA = 2; }
    if (la3 > mA) { mA = la3; selA = 3; }
    int selB = 0; float mB = lb0;
    if (lb1 > mB) { mB = lb1; selB = 1; }
    if (lb2 > mB) { mB = lb2; selB = 2; }
    if (lb3 > mB) { mB = lb3; selB = 3; }

    u64 oA0, oA1, oA2, oB0, oB1, oB2;
    expert_eval(s, xa, selA, oA0, oA1, oA2);
    expert_eval(s, xb, selB, oB0, oB1, oB2);

    {
        u64* p0 = (u64*)(pred + (size_t)ba * OO);
        p0[0] = oA0; p0[1] = oA1; p0[2] = oA2;
        u64* p1 = (u64*)(pred + (size_t)bb * OO);
        p1[0] = oB0; p1[1] = oB1; p1[2] = oB2;
        ulonglong2* l0 = (ulonglong2*)(glog + (size_t)ba * EE);
        l0[0] = make_ulonglong2(lgA0, lgA1);
        ulonglong2* l1 = (ulonglong2*)(glog + (size_t)bb * EE);
        l1[0] = make_ulonglong2(lgB0, lgB1);
    }
}

extern "C" void kernel_launch(void* const* d_in, const int* in_sizes, int n_in,
                              void* d_out, int out_size) {
    const float* x   = (const float*)d_in[0];
    const float* eW1 = (const float*)d_in[1];
    const float* eb1 = (const float*)d_in[2];
    const float* eW2 = (const float*)d_in[3];
    const float* eb2 = (const float*)d_in[4];
    const float* eW3 = (const float*)d_in[5];
    const float* eb3 = (const float*)d_in[6];
    const float* gW1 = (const float*)d_in[7];
    const float* gb1 = (const float*)d_in[8];
    const float* gW2 = (const float*)d_in[9];
    const float* gb2 = (const float*)d_in[10];
    const float* gW3 = (const float*)d_in[11];
    const float* gb3 = (const float*)d_in[12];

    // two const staging nodes only
    cudaMemcpyToSymbolAsync(cw, gW1, 1088 * 4, C_GW1 * 4, cudaMemcpyDeviceToDevice);
    cudaMemcpyToSymbolAsync(cw, gW2, 2048 * 4, C_GW2 * 4, cudaMemcpyDeviceToDevice);

    const int B = in_sizes[0] / DD;
    float* out  = (float*)d_out;
    float* pred = out;                   // [B, 6]
    float* glog = out + (size_t)B * OO;  // [B, 4]

    const int grid = B / 256;            // 128 threads/block, 2 samples/thread
    moe_kernel<<<grid, 128>>>(x, eW1, eb1, eW2, eb2, eW3, eb3,
                              gb1, gb2, gW3, gb3, pred, glog, B / 2);
}